// round 4
// baseline (speedup 1.0000x reference)
#include <cuda_runtime.h>
#include <cuda_bf16.h>
#include <cstdint>

#define N_NODES 50000
#define N_EDGES 800000
#define DIM     128

#define BNT      64                       // nodes per CTA tile
#define N_TILES  ((N_NODES + BNT - 1) / BNT)   // 782 (tail tile: 16 valid)
#define BR_THREADS 256
// SMEM: W 64KB + X 32KB + bias/scale/offset 1.5KB + LN partials 2KB
#define BR_SMEM (65536 + 32768 + 3*512 + BNT*4*8)

using u64 = unsigned long long;

__device__ __forceinline__ void ffma2(u64& d, u64 a, u64 b) {
    asm("fma.rn.f32x2 %0, %1, %2, %0;" : "+l"(d) : "l"(a), "l"(b));
}
__device__ __forceinline__ float2 unpack2(u64 v) {
    float2 r;
    asm("mov.b64 {%0,%1}, %2;" : "=f"(r.x), "=f"(r.y) : "l"(v));
    return r;
}

__device__ float g_neigh[(size_t)N_NODES * DIM];

// ---------------------------------------------------------------------------
__global__ void zero_kernel(float4* __restrict__ p, int n4) {
    int i = blockIdx.x * blockDim.x + threadIdx.x;
    if (i < n4) p[i] = make_float4(0.f, 0.f, 0.f, 0.f);
}

// ---------------------------------------------------------------------------
// edge scatter: one warp per edge, lane = float4 of 4 dims. LTS-bound.
// ---------------------------------------------------------------------------
__global__ void scatter_kernel(const float* __restrict__ feat,
                               const int*   __restrict__ erow,
                               const int*   __restrict__ ecol,
                               const float* __restrict__ eval_,
                               float*       __restrict__ neigh) {
    int warp_id = (blockIdx.x * blockDim.x + threadIdx.x) >> 5;
    int lane    = threadIdx.x & 31;
    if (warp_id >= N_EDGES) return;
    int   r = erow[warp_id];
    int   c = ecol[warp_id];
    float v = eval_[warp_id];

    const float4* src = (const float4*)(feat + (size_t)c * DIM);
    float4 x = src[lane];
    float4 y;
    y.x = x.x * v; y.y = x.y * v; y.z = x.z * v; y.w = x.w * v;

    float* dst = neigh + (size_t)r * DIM + lane * 4;
    asm volatile("red.global.add.v4.f32 [%0], {%1,%2,%3,%4};"
                 :: "l"(dst), "f"(y.x), "f"(y.y), "f"(y.z), "f"(y.w)
                 : "memory");
}

// ---------------------------------------------------------------------------
// fused branch: out (+)= LN(relu(X @ W^T + b)) * scale + offset
//
// CTA tile 64 nodes x 128 dims; 8 warps = 2 node-groups x 4 dim-groups;
// warp tile 32x32. Thread (mi = lane&7, nj = lane>>3) owns 4 nodes x 8 dims,
// accumulators packed over K (fma.rn.f32x2, even/odd-k partials).
// Per k4 step: 4 X LDS.128 (4-way bcast) + 8 W LDS.128 (8-way bcast) feed
// 64 FFMA2 -> crossbar ~0.25 B/laneFMA, fma-pipe bound.
// LN: intra-warp shuffle (xor 8,16) + cross-dim-group partials in SMEM.
// ---------------------------------------------------------------------------
template<bool ACC>
__global__ void __launch_bounds__(BR_THREADS, 2) branch_kernel(
    const float* __restrict__ X, const float* __restrict__ W,
    const float* __restrict__ bias, const float* __restrict__ scale,
    const float* __restrict__ offset, int so, float* __restrict__ out)
{
    extern __shared__ char smem[];
    ulonglong2* sW  = (ulonglong2*)smem;                    // [128][32] swizzled
    ulonglong2* sX  = (ulonglong2*)(smem + 65536);          // [64][32]  swizzled
    float*      sB  = (float*)(smem + 65536 + 32768);       // 128
    float*      sS  = sB + 128;
    float*      sO  = sS + 128;
    float2*     sPQ = (float2*)(sO + 128);                  // [64][4]

    const int tid  = threadIdx.x;
    const int lane = tid & 31;
    const int wid  = tid >> 5;
    const int dg   = wid & 3;          // dim-group 0..3
    const int ng   = wid >> 2;         // node-group 0..1
    const int mi   = lane & 7;
    const int nj   = lane >> 3;
    const int rb   = ng * 32 + mi * 4; // local node base (4 nodes)
    const int j0   = dg * 32 + nj * 8; // output-dim base (8 dims)
    const int gbase = blockIdx.x * BNT;

    // W swizzled: row j, chunk k4 at (j<<5) | (k4 ^ ((j>>3)&7)).
    const ulonglong2* Wg = (const ulonglong2*)W;
    for (int i = tid; i < DIM * 32; i += BR_THREADS) {
        int j = i >> 5, k4 = i & 31;
        sW[(j << 5) | (k4 ^ ((j >> 3) & 7))] = Wg[i];
    }
    // X swizzled: row r, chunk k4 at (r<<5) | (k4 ^ ((r>>2)&31)); clamp tail rows.
    for (int i = tid; i < BNT * 32; i += BR_THREADS) {
        int r = i >> 5, k4 = i & 31;
        int gr = gbase + r; if (gr >= N_NODES) gr = N_NODES - 1;
        sX[(r << 5) | (k4 ^ ((r >> 2) & 31))] =
            ((const ulonglong2*)X)[(size_t)gr * 32 + k4];
    }
    if (tid < 32)       ((float4*)sB)[tid]      = ((const float4*)bias)[tid];
    else if (tid < 64)  ((float4*)sS)[tid - 32] = ((const float4*)(scale  + so))[tid - 32];
    else if (tid < 96)  ((float4*)sO)[tid - 64] = ((const float4*)(offset + so))[tid - 64];
    __syncthreads();

    u64 acc[4][8];
#pragma unroll
    for (int m = 0; m < 4; m++)
#pragma unroll
        for (int d = 0; d < 8; d++) acc[m][d] = 0ull;

    const int xc = (rb >> 2) & 31;      // same for all 4 owned nodes
    const int wc = (j0 >> 3) & 7;       // same for all 8 owned dims

#pragma unroll 4
    for (int k4 = 0; k4 < 32; k4++) {
        const int kx = k4 ^ xc;
        const int kw = k4 ^ wc;
        ulonglong2 x0 = sX[((rb + 0) << 5) | kx];
        ulonglong2 x1 = sX[((rb + 1) << 5) | kx];
        ulonglong2 x2 = sX[((rb + 2) << 5) | kx];
        ulonglong2 x3 = sX[((rb + 3) << 5) | kx];
#pragma unroll
        for (int d = 0; d < 8; d++) {
            ulonglong2 w = sW[((j0 + d) << 5) | kw];
            ffma2(acc[0][d], w.x, x0.x); ffma2(acc[0][d], w.y, x0.y);
            ffma2(acc[1][d], w.x, x1.x); ffma2(acc[1][d], w.y, x1.y);
            ffma2(acc[2][d], w.x, x2.x); ffma2(acc[2][d], w.y, x2.y);
            ffma2(acc[3][d], w.x, x3.x); ffma2(acc[3][d], w.y, x3.y);
        }
    }

    // ReLU + per-node partial sums over this thread's 8 dims
    float h[4][8];
    float sp[4], qp[4];
#pragma unroll
    for (int m = 0; m < 4; m++) {
        float s = 0.f, q = 0.f;
#pragma unroll
        for (int d = 0; d < 8; d++) {
            float2 p = unpack2(acc[m][d]);
            float v = fmaxf(p.x + p.y + sB[j0 + d], 0.f);
            h[m][d] = v;
            s += v; q = fmaf(v, v, q);
        }
        sp[m] = s; qp[m] = q;
    }
    // reduce over nj (lanes xor 8,16) -> sums over this warp's 32 dims
#pragma unroll
    for (int m = 0; m < 4; m++) {
        sp[m] += __shfl_xor_sync(0xffffffffu, sp[m], 8);
        qp[m] += __shfl_xor_sync(0xffffffffu, qp[m], 8);
        sp[m] += __shfl_xor_sync(0xffffffffu, sp[m], 16);
        qp[m] += __shfl_xor_sync(0xffffffffu, qp[m], 16);
    }
    if (nj == 0) {
#pragma unroll
        for (int m = 0; m < 4; m++)
            sPQ[(rb + m) * 4 + dg] = make_float2(sp[m], qp[m]);
    }
    __syncthreads();

    // finalize LN per node, apply affine, (optional) accumulate, store
    const float4 sc0 = *(const float4*)(sS + j0);
    const float4 sc1 = *(const float4*)(sS + j0 + 4);
    const float4 of0 = *(const float4*)(sO + j0);
    const float4 of1 = *(const float4*)(sO + j0 + 4);

#pragma unroll
    for (int m = 0; m < 4; m++) {
        const int r = rb + m;
        float2 t0 = sPQ[r * 4 + 0], t1 = sPQ[r * 4 + 1];
        float2 t2 = sPQ[r * 4 + 2], t3 = sPQ[r * 4 + 3];
        float s = t0.x + t1.x + t2.x + t3.x;
        float q = t0.y + t1.y + t2.y + t3.y;
        float mean = s * (1.f / DIM);
        float var  = q * (1.f / DIM) - mean * mean + 1e-9f;
        float rs   = rsqrtf(var);

        int gnode = gbase + r;
        if (gnode < N_NODES) {
            float4 r0, r1;
            r0.x = (h[m][0] - mean) * rs * sc0.x + of0.x;
            r0.y = (h[m][1] - mean) * rs * sc0.y + of0.y;
            r0.z = (h[m][2] - mean) * rs * sc0.z + of0.z;
            r0.w = (h[m][3] - mean) * rs * sc0.w + of0.w;
            r1.x = (h[m][4] - mean) * rs * sc1.x + of1.x;
            r1.y = (h[m][5] - mean) * rs * sc1.y + of1.y;
            r1.z = (h[m][6] - mean) * rs * sc1.z + of1.z;
            r1.w = (h[m][7] - mean) * rs * sc1.w + of1.w;

            float4* op = (float4*)(out + (size_t)gnode * DIM + j0);
            if (ACC) {
                float4 p0 = op[0], p1 = op[1];
                r0.x += p0.x; r0.y += p0.y; r0.z += p0.z; r0.w += p0.w;
                r1.x += p1.x; r1.y += p1.y; r1.z += p1.z; r1.w += p1.w;
            }
            op[0] = r0; op[1] = r1;
        }
    }
}

// ---------------------------------------------------------------------------
struct ForkResources {
    cudaStream_t s2  = nullptr;
    cudaEvent_t  ev1 = nullptr, ev2 = nullptr;
    bool ok = false;
    ForkResources() {
        if (cudaStreamCreateWithFlags(&s2, cudaStreamNonBlocking) != cudaSuccess) return;
        if (cudaEventCreateWithFlags(&ev1, cudaEventDisableTiming) != cudaSuccess) return;
        if (cudaEventCreateWithFlags(&ev2, cudaEventDisableTiming) != cudaSuccess) return;
        ok = true;
    }
};
static ForkResources g_fork;

// ---------------------------------------------------------------------------
// stream0: zero -> scatter ----\
// s2:      branch_self ---------- join -> branch_neigh(ACC)
// ---------------------------------------------------------------------------
extern "C" void kernel_launch(void* const* d_in, const int* in_sizes, int n_in,
                              void* d_out, int out_size) {
    const float* feat_in  = (const float*)d_in[0];
    const int*   edge_row = (const int*)  d_in[1];
    const int*   edge_col = (const int*)  d_in[2];
    const float* edge_val = (const float*)d_in[3];
    const float* W_self   = (const float*)d_in[4];
    const float* b_self   = (const float*)d_in[5];
    const float* W_neigh  = (const float*)d_in[6];
    const float* b_neigh  = (const float*)d_in[7];
    const float* scale    = (const float*)d_in[8];
    const float* offset   = (const float*)d_in[9];
    float* out = (float*)d_out;

    float* neigh = nullptr;
    cudaGetSymbolAddress((void**)&neigh, g_neigh);

    cudaFuncSetAttribute(branch_kernel<false>,
                         cudaFuncAttributeMaxDynamicSharedMemorySize, BR_SMEM);
    cudaFuncSetAttribute(branch_kernel<true>,
                         cudaFuncAttributeMaxDynamicSharedMemorySize, BR_SMEM);

    const int n4 = N_NODES * DIM / 4;
    const int scatter_blocks = (N_EDGES * 32) / 256;

    if (g_fork.ok) {
        cudaEventRecord(g_fork.ev1, 0);
        cudaStreamWaitEvent(g_fork.s2, g_fork.ev1, 0);

        branch_kernel<false><<<N_TILES, BR_THREADS, BR_SMEM, g_fork.s2>>>(
            feat_in, W_self, b_self, scale, offset, 0, out);

        zero_kernel<<<(n4 + 255) / 256, 256>>>((float4*)neigh, n4);
        scatter_kernel<<<scatter_blocks, 256>>>(feat_in, edge_row, edge_col, edge_val, neigh);

        cudaEventRecord(g_fork.ev2, g_fork.s2);
        cudaStreamWaitEvent(0, g_fork.ev2, 0);

        branch_kernel<true><<<N_TILES, BR_THREADS, BR_SMEM>>>(
            neigh, W_neigh, b_neigh, scale, offset, DIM, out);
    } else {
        zero_kernel<<<(n4 + 255) / 256, 256>>>((float4*)neigh, n4);
        branch_kernel<false><<<N_TILES, BR_THREADS, BR_SMEM>>>(
            feat_in, W_self, b_self, scale, offset, 0, out);
        scatter_kernel<<<scatter_blocks, 256>>>(feat_in, edge_row, edge_col, edge_val, neigh);
        branch_kernel<true><<<N_TILES, BR_THREADS, BR_SMEM>>>(
            neigh, W_neigh, b_neigh, scale, offset, DIM, out);
    }
}